// round 14
// baseline (speedup 1.0000x reference)
#include <cuda_runtime.h>
#include <cstdint>

// Problem constants
#define KK    8
#define RR    200000
#define CIN   32
#define COUT  32
#define NOUT  400000
#define TPB   512        // rules per block
#define NTHR  128        // 4 warps
#define WARPS 4
#define RPW   16         // rules per warp-tile
#define TILE  (WARPS * RPW)   // 64 rules per block iteration

// smem layout (bytes)
#define AROW    80                  // A row pitch (16B-mult, ldmatrix conflict-free)
#define A_PLANE (16 * AROW)         // 1280 (one bf16 plane, 16 rows)
#define A_WARP  (2 * A_PLANE)       // 2560 (hi + lo planes)
#define OFF_A   0                   // 4 warps -> 10240
#define OFF_RIN  10240              // 512 ints
#define OFF_ROUT 12288              // 512 ints
#define SMEM_BYTES 14336

// ---------------------------------------------------------------------------
// helpers
// ---------------------------------------------------------------------------
__device__ __forceinline__ uint32_t smem_u32(const void* p) {
    uint32_t a;
    asm("{ .reg .u64 t; cvta.to.shared.u64 t, %1; cvt.u32.u64 %0, t; }" : "=r"(a) : "l"(p));
    return a;
}
__device__ __forceinline__ uint32_t cvt_bf16x2(float hi, float lo) {  // (hi<<16)|lo
    uint32_t r;
    asm("cvt.rn.bf16x2.f32 %0, %1, %2;" : "=r"(r) : "f"(hi), "f"(lo));
    return r;
}
__device__ __forceinline__ void sts64(uint32_t a, uint32_t x, uint32_t y) {
    asm volatile("st.shared.v2.b32 [%0], {%1,%2};" :: "r"(a), "r"(x), "r"(y));
}
__device__ __forceinline__ void red4(float* addr, float a, float b, float c, float d) {
    asm volatile("red.global.add.v4.f32 [%0], {%1,%2,%3,%4};"
                 :: "l"(addr), "f"(a), "f"(b), "f"(c), "f"(d) : "memory");
}
__device__ __forceinline__ void ldmx4(uint32_t* r, uint32_t addr) {
    asm volatile("ldmatrix.sync.aligned.m8n8.x4.shared.b16 {%0,%1,%2,%3}, [%4];"
                 : "=r"(r[0]), "=r"(r[1]), "=r"(r[2]), "=r"(r[3]) : "r"(addr));
}
__device__ __forceinline__ void mma_bf16(float* d, const uint32_t* a, const uint32_t* b) {
    asm volatile("mma.sync.aligned.m16n8k16.row.col.f32.bf16.bf16.f32 "
                 "{%0,%1,%2,%3}, {%4,%5,%6,%7}, {%8,%9}, {%0,%1,%2,%3};"
                 : "+f"(d[0]), "+f"(d[1]), "+f"(d[2]), "+f"(d[3])
                 : "r"(a[0]), "r"(a[1]), "r"(a[2]), "r"(a[3]), "r"(b[0]), "r"(b[1]));
}

// ---------------------------------------------------------------------------
// Kernel 1: initialize output to bias
// ---------------------------------------------------------------------------
__global__ void init_out_kernel(float* __restrict__ out,
                                const float* __restrict__ bias) {
    int idx = blockIdx.x * blockDim.x + threadIdx.x;
    const int total4 = NOUT * COUT / 4;
    if (idx < total4) {
        int c = (idx & 7) * 4;
        float4 v = make_float4(bias[c], bias[c + 1], bias[c + 2], bias[c + 3]);
        reinterpret_cast<float4*>(out)[idx] = v;
    }
}

// ---------------------------------------------------------------------------
// Kernel 2: gather -> bf16 hi/lo split -> mma.sync -> shfl pair-exchange
//           -> v4 RED straight from registers (no smem transpose)
// ---------------------------------------------------------------------------
__global__ void __launch_bounds__(NTHR, 6)
mma_scatter_kernel(const float* __restrict__ feats,
                   const float* __restrict__ weight,
                   const int*   __restrict__ rules_in,
                   const int*   __restrict__ rules_out,
                   float*       __restrict__ out)
{
    __shared__ __align__(128) char smem[SMEM_BYTES];
    const uint32_t sb = smem_u32(smem);
    const int tid  = threadIdx.x;
    const int lane = tid & 31;
    const int wid  = tid >> 5;
    const int g    = lane >> 2;       // mma group row (0..7)
    const int t    = lane & 3;        // thread-in-group
    const int k    = blockIdx.y;
    const int base = blockIdx.x * TPB;
    const int nblk = min(TPB, RR - base);
    const int nit  = nblk / TILE;     // exact (512/64=8; tail 320/64=5)

    int* sRin  = (int*)(smem + OFF_RIN);
    int* sRout = (int*)(smem + OFF_ROUT);

    // Stage rule indices (one int4 per thread covers TPB=512)
    {
        const int4* rin4  = (const int4*)(rules_in  + k * RR + base);
        const int4* rout4 = (const int4*)(rules_out + k * RR + base);
        if (tid * 4 < nblk) {
            ((int4*)sRin)[tid]  = __ldg(rin4  + tid);
            ((int4*)sRout)[tid] = __ldg(rout4 + tid);
        }
    }

    // Weight fragments (hi/lo split), B col-major for m16n8k16:
    //   reg0 = (B[k0+1][o]<<16)|B[k0][o], reg1 = (B[k0+9][o]<<16)|B[k0+8][o]
    //   k0 = kc*16 + 2t, o = n*8 + g
    uint32_t WH[4][2][2], WL[4][2][2];
    {
        const float* wk = weight + (size_t)k * CIN * COUT;
        #pragma unroll
        for (int n = 0; n < 4; n++)
            #pragma unroll
            for (int kc = 0; kc < 2; kc++) {
                int o  = n * 8 + g;
                int k0 = kc * 16 + 2 * t;
                float w00 = __ldg(wk + (k0 + 0) * COUT + o);
                float w01 = __ldg(wk + (k0 + 1) * COUT + o);
                float w10 = __ldg(wk + (k0 + 8) * COUT + o);
                float w11 = __ldg(wk + (k0 + 9) * COUT + o);
                uint32_t h0 = cvt_bf16x2(w01, w00);
                uint32_t h1 = cvt_bf16x2(w11, w10);
                WH[n][kc][0] = h0;
                WH[n][kc][1] = h1;
                float r00 = w00 - __uint_as_float(h0 << 16);
                float r01 = w01 - __uint_as_float(h0 & 0xFFFF0000u);
                float r10 = w10 - __uint_as_float(h1 << 16);
                float r11 = w11 - __uint_as_float(h1 & 0xFFFF0000u);
                WL[n][kc][0] = cvt_bf16x2(r01, r00);
                WL[n][kc][1] = cvt_bf16x2(r11, r10);
            }
    }
    __syncthreads();   // indices staged

    const uint32_t sAw = sb + OFF_A + wid * A_WARP;

    // ldmatrix lane address: 4 tiles of 8x8 covering 16 rows x 16 cols (bf16)
    const int lm_row = (lane & 7) + ((lane >> 3) & 1) * 8;
    const int lm_col = (lane >> 4) * 16;
    const uint32_t lm_base = sAw + lm_row * AROW + lm_col;

    // Per-lane gather slots: row = i*4 + (lane>>3), seg = lane&7
    const int g_row = lane >> 3;
    const int g_seg = lane & 7;

    // Epilogue lane role: even t -> rule g, odd t -> rule g+8
    const bool oddt = (t & 1);
    const int  col0 = 2 * (t & ~1);      // 0 or 4: base col within n-block

    float4 gbuf[4];
    auto do_gather = [&](int it) {
        #pragma unroll
        for (int i = 0; i < 4; i++) {
            int r = sRin[it * TILE + wid * RPW + i * 4 + g_row];
            gbuf[i] = __ldg((const float4*)(feats + (size_t)r * CIN) + g_seg);
        }
    };
    do_gather(0);

    for (int it = 0; it < nit; it++) {
        // ---- convert gathered f32 -> bf16 hi/lo planes in smem
        #pragma unroll
        for (int i = 0; i < 4; i++) {
            int row = i * 4 + g_row;
            float4 v = gbuf[i];
            uint32_t h0 = cvt_bf16x2(v.y, v.x);
            uint32_t h1 = cvt_bf16x2(v.w, v.z);
            float hx = __uint_as_float(h0 << 16);
            float hy = __uint_as_float(h0 & 0xFFFF0000u);
            float hz = __uint_as_float(h1 << 16);
            float hw = __uint_as_float(h1 & 0xFFFF0000u);
            uint32_t l0 = cvt_bf16x2(v.y - hy, v.x - hx);
            uint32_t l1 = cvt_bf16x2(v.w - hw, v.z - hz);
            sts64(sAw + row * AROW + g_seg * 8,           h0, h1);
            sts64(sAw + A_PLANE + row * AROW + g_seg * 8, l0, l1);
        }
        if (it + 1 < nit) do_gather(it + 1);   // overlap LDG with mma/epilogue
        __syncwarp();

        // ---- load A fragments (hi and lo planes, 2 K-chunks each)
        uint32_t ah[2][4], al[2][4];
        ldmx4(ah[0], lm_base);
        ldmx4(ah[1], lm_base + 32);
        ldmx4(al[0], lm_base + A_PLANE);
        ldmx4(al[1], lm_base + A_PLANE + 32);
        __syncwarp();   // A smem consumed; next tile's STS free to proceed

        // Scatter base pointer for this lane's rule (even t: g, odd t: g+8)
        int my_rule = sRout[it * TILE + wid * RPW + g + (oddt ? 8 : 0)];
        float* obase = out + (size_t)my_rule * COUT + col0;

        // ---- per-n: 6 mma -> pair exchange (shfl xor 1) -> direct v4 RED
        // D[0,1] = rule g cols (n*8+2t, +1); D[2,3] = rule g+8 same cols
        #pragma unroll
        for (int n = 0; n < 4; n++) {
            float D[4] = {0.f, 0.f, 0.f, 0.f};
            #pragma unroll
            for (int kc = 0; kc < 2; kc++) {
                mma_bf16(D, ah[kc], WH[n][kc]);
                mma_bf16(D, al[kc], WH[n][kc]);
                mma_bf16(D, ah[kc], WL[n][kc]);
            }
            float p0 = __shfl_xor_sync(0xFFFFFFFFu, D[0], 1);
            float p1 = __shfl_xor_sync(0xFFFFFFFFu, D[1], 1);
            float p2 = __shfl_xor_sync(0xFFFFFFFFu, D[2], 1);
            float p3 = __shfl_xor_sync(0xFFFFFFFFu, D[3], 1);
            // even t: rule g   cols n*8+col0.. = {D0, D1, p0, p1}
            // odd  t: rule g+8 cols n*8+col0.. = {p2, p3, D2, D3}
            float v0 = oddt ? p2 : D[0];
            float v1 = oddt ? p3 : D[1];
            float v2 = oddt ? D[2] : p0;
            float v3 = oddt ? D[3] : p1;
            red4(obase + n * 8, v0, v1, v2, v3);
        }
    }
}

// ---------------------------------------------------------------------------
extern "C" void kernel_launch(void* const* d_in, const int* in_sizes, int n_in,
                              void* d_out, int out_size) {
    const float* feats  = (const float*)d_in[0];
    const float* weight = (const float*)d_in[1];
    const float* bias   = (const float*)d_in[2];
    const int*   rin    = (const int*)  d_in[3];
    const int*   rout   = (const int*)  d_in[4];
    float* out = (float*)d_out;

    const int total4 = NOUT * COUT / 4;
    init_out_kernel<<<(total4 + 255) / 256, 256>>>(out, bias);

    dim3 grid((RR + TPB - 1) / TPB, KK);
    mma_scatter_kernel<<<grid, NTHR>>>(feats, weight, rin, rout, out);
}

// round 16
// speedup vs baseline: 1.2689x; 1.2689x over previous
#include <cuda_runtime.h>
#include <cstdint>

// Problem constants
#define KK    8
#define RR    200000
#define CIN   32
#define COUT  32
#define NOUT  400000
#define TPB   512        // rules per block
#define NTHR  128        // 4 warps
#define WARPS 4
#define RPW   16         // rules per warp-tile
#define TILE  (WARPS * RPW)   // 64 rules per block iteration

// smem layout (bytes)
#define AROW    80                  // A row pitch (16B-mult, ldmatrix conflict-free)
#define A_PLANE (16 * AROW)         // 1280 (one bf16 plane, 16 rows)
#define A_WARP  (2 * A_PLANE)       // 2560 (hi + lo planes)
#define OFF_A   0                   // 4 warps -> 10240
#define TROWF   36                  // transpose row pitch in floats (144B)
#define T_WARP  (16 * TROWF * 4)    // 2304
#define OFF_T   10240               // 4 warps -> 9216, end 19456
#define OFF_RIN  19456              // 512 ints
#define OFF_ROUT 21504              // 512 ints
#define SMEM_BYTES 23552

// ---------------------------------------------------------------------------
// helpers
// ---------------------------------------------------------------------------
__device__ __forceinline__ uint32_t smem_u32(const void* p) {
    uint32_t a;
    asm("{ .reg .u64 t; cvta.to.shared.u64 t, %1; cvt.u32.u64 %0, t; }" : "=r"(a) : "l"(p));
    return a;
}
__device__ __forceinline__ uint32_t cvt_bf16x2(float hi, float lo) {  // (hi<<16)|lo
    uint32_t r;
    asm("cvt.rn.bf16x2.f32 %0, %1, %2;" : "=r"(r) : "f"(hi), "f"(lo));
    return r;
}
__device__ __forceinline__ void sts64(uint32_t a, uint32_t x, uint32_t y) {
    asm volatile("st.shared.v2.b32 [%0], {%1,%2};" :: "r"(a), "r"(x), "r"(y));
}
__device__ __forceinline__ void red4(float* addr, float a, float b, float c, float d) {
    asm volatile("red.global.add.v4.f32 [%0], {%1,%2,%3,%4};"
                 :: "l"(addr), "f"(a), "f"(b), "f"(c), "f"(d) : "memory");
}
__device__ __forceinline__ void ldmx4(uint32_t* r, uint32_t addr) {
    asm volatile("ldmatrix.sync.aligned.m8n8.x4.shared.b16 {%0,%1,%2,%3}, [%4];"
                 : "=r"(r[0]), "=r"(r[1]), "=r"(r[2]), "=r"(r[3]) : "r"(addr));
}
__device__ __forceinline__ void mma_bf16(float* d, const uint32_t* a, const uint32_t* b) {
    asm volatile("mma.sync.aligned.m16n8k16.row.col.f32.bf16.bf16.f32 "
                 "{%0,%1,%2,%3}, {%4,%5,%6,%7}, {%8,%9}, {%0,%1,%2,%3};"
                 : "+f"(d[0]), "+f"(d[1]), "+f"(d[2]), "+f"(d[3])
                 : "r"(a[0]), "r"(a[1]), "r"(a[2]), "r"(a[3]), "r"(b[0]), "r"(b[1]));
}
// Streaming (evict-first) loads: use-once data must not evict the L2-resident output
__device__ __forceinline__ float4 ldcs4(const float4* p) {
    float4 v;
    asm volatile("ld.global.cs.v4.f32 {%0,%1,%2,%3}, [%4];"
                 : "=f"(v.x), "=f"(v.y), "=f"(v.z), "=f"(v.w) : "l"(p));
    return v;
}
__device__ __forceinline__ int4 ldcsi4(const int4* p) {
    int4 v;
    asm volatile("ld.global.cs.v4.b32 {%0,%1,%2,%3}, [%4];"
                 : "=r"(v.x), "=r"(v.y), "=r"(v.z), "=r"(v.w) : "l"(p));
    return v;
}

// ---------------------------------------------------------------------------
// Kernel 1: initialize output to bias
// ---------------------------------------------------------------------------
__global__ void init_out_kernel(float* __restrict__ out,
                                const float* __restrict__ bias) {
    int idx = blockIdx.x * blockDim.x + threadIdx.x;
    const int total4 = NOUT * COUT / 4;
    if (idx < total4) {
        int c = (idx & 7) * 4;
        float4 v = make_float4(bias[c], bias[c + 1], bias[c + 2], bias[c + 3]);
        reinterpret_cast<float4*>(out)[idx] = v;
    }
}

// ---------------------------------------------------------------------------
// Kernel 2: gather (streaming) -> bf16 hi/lo split -> mma.sync
//           -> smem transpose -> line-coalesced v4 RED   (R7 structure)
// ---------------------------------------------------------------------------
__global__ void __launch_bounds__(NTHR)
mma_scatter_kernel(const float* __restrict__ feats,
                   const float* __restrict__ weight,
                   const int*   __restrict__ rules_in,
                   const int*   __restrict__ rules_out,
                   float*       __restrict__ out)
{
    __shared__ __align__(128) char smem[SMEM_BYTES];
    const uint32_t sb = smem_u32(smem);
    const int tid  = threadIdx.x;
    const int lane = tid & 31;
    const int wid  = tid >> 5;
    const int g    = lane >> 2;       // mma group row
    const int t    = lane & 3;        // thread-in-group
    const int k    = blockIdx.y;
    const int base = blockIdx.x * TPB;
    const int nblk = min(TPB, RR - base);
    const int nit  = nblk / TILE;     // exact for these sizes

    int* sRin  = (int*)(smem + OFF_RIN);
    int* sRout = (int*)(smem + OFF_ROUT);

    // Stage rule indices (one int4 per thread covers TPB=512) — streaming
    {
        const int4* rin4  = (const int4*)(rules_in  + k * RR + base);
        const int4* rout4 = (const int4*)(rules_out + k * RR + base);
        if (tid * 4 < nblk) {
            ((int4*)sRin)[tid]  = ldcsi4(rin4  + tid);
            ((int4*)sRout)[tid] = ldcsi4(rout4 + tid);
        }
    }

    // Weight fragments (hi/lo split), B col-major for m16n8k16:
    //   reg0 = (B[k0+1][o]<<16)|B[k0][o], reg1 = (B[k0+9][o]<<16)|B[k0+8][o]
    //   k0 = kc*16 + 2t, o = n*8 + g
    uint32_t WH[4][2][2], WL[4][2][2];
    {
        const float* wk = weight + (size_t)k * CIN * COUT;
        #pragma unroll
        for (int n = 0; n < 4; n++)
            #pragma unroll
            for (int kc = 0; kc < 2; kc++) {
                int o  = n * 8 + g;
                int k0 = kc * 16 + 2 * t;
                float w00 = __ldg(wk + (k0 + 0) * COUT + o);
                float w01 = __ldg(wk + (k0 + 1) * COUT + o);
                float w10 = __ldg(wk + (k0 + 8) * COUT + o);
                float w11 = __ldg(wk + (k0 + 9) * COUT + o);
                uint32_t h0 = cvt_bf16x2(w01, w00);
                uint32_t h1 = cvt_bf16x2(w11, w10);
                WH[n][kc][0] = h0;
                WH[n][kc][1] = h1;
                float r00 = w00 - __uint_as_float(h0 << 16);
                float r01 = w01 - __uint_as_float(h0 & 0xFFFF0000u);
                float r10 = w10 - __uint_as_float(h1 << 16);
                float r11 = w11 - __uint_as_float(h1 & 0xFFFF0000u);
                WL[n][kc][0] = cvt_bf16x2(r01, r00);
                WL[n][kc][1] = cvt_bf16x2(r11, r10);
            }
    }
    __syncthreads();   // indices staged

    const uint32_t sAw = sb + OFF_A + wid * A_WARP;
    const uint32_t sTw = sb + OFF_T + wid * T_WARP;
    float* sTwp = (float*)(smem + OFF_T + wid * T_WARP);

    // ldmatrix lane address: 4 tiles of 8x8 covering 16 rows x 16 cols (bf16)
    const int lm_row = (lane & 7) + ((lane >> 3) & 1) * 8;
    const int lm_col = (lane >> 4) * 16;
    const uint32_t lm_base = sAw + lm_row * AROW + lm_col;

    // Per-lane gather slots: row = i*4 + (lane>>3), seg = lane&7
    const int g_row = lane >> 3;
    const int g_seg = lane & 7;

    float4 gbuf[4];
    auto do_gather = [&](int it) {
        #pragma unroll
        for (int i = 0; i < 4; i++) {
            int r = sRin[it * TILE + wid * RPW + i * 4 + g_row];
            gbuf[i] = ldcs4((const float4*)(feats + (size_t)r * CIN) + g_seg);
        }
    };
    do_gather(0);

    for (int it = 0; it < nit; it++) {
        // ---- convert gathered f32 -> bf16 hi/lo planes in smem
        #pragma unroll
        for (int i = 0; i < 4; i++) {
            int row = i * 4 + g_row;
            float4 v = gbuf[i];
            uint32_t h0 = cvt_bf16x2(v.y, v.x);
            uint32_t h1 = cvt_bf16x2(v.w, v.z);
            float hx = __uint_as_float(h0 << 16);
            float hy = __uint_as_float(h0 & 0xFFFF0000u);
            float hz = __uint_as_float(h1 << 16);
            float hw = __uint_as_float(h1 & 0xFFFF0000u);
            uint32_t l0 = cvt_bf16x2(v.y - hy, v.x - hx);
            uint32_t l1 = cvt_bf16x2(v.w - hw, v.z - hz);
            sts64(sAw + row * AROW + g_seg * 8,           h0, h1);
            sts64(sAw + A_PLANE + row * AROW + g_seg * 8, l0, l1);
        }
        if (it + 1 < nit) do_gather(it + 1);   // overlap LDG with mma/epilogue
        __syncwarp();

        // ---- load A fragments (hi and lo planes, 2 K-chunks each)
        uint32_t ah[2][4], al[2][4];
        ldmx4(ah[0], lm_base);
        ldmx4(ah[1], lm_base + 32);
        ldmx4(al[0], lm_base + A_PLANE);
        ldmx4(al[1], lm_base + A_PLANE + 32);

        // ---- 24 mma: D[n] = sum_kc Ah*Wh + Al*Wh + Ah*Wl
        float D[4][4] = {};
        #pragma unroll
        for (int n = 0; n < 4; n++)
            #pragma unroll
            for (int kc = 0; kc < 2; kc++) {
                mma_bf16(D[n], ah[kc], WH[n][kc]);
                mma_bf16(D[n], al[kc], WH[n][kc]);
                mma_bf16(D[n], ah[kc], WL[n][kc]);
            }

        // ---- epilogue: fragments -> smem transpose -> coalesced v4 RED
        // D[n][0,1] = rule g,   cols n*8+2t, +1
        // D[n][2,3] = rule g+8, cols n*8+2t, +1
        #pragma unroll
        for (int n = 0; n < 4; n++) {
            int col = n * 8 + 2 * t;
            sts64(sTw + (g * TROWF + col) * 4,
                  __float_as_uint(D[n][0]), __float_as_uint(D[n][1]));
            sts64(sTw + ((g + 8) * TROWF + col) * 4,
                  __float_as_uint(D[n][2]), __float_as_uint(D[n][3]));
        }
        __syncwarp();

        #pragma unroll
        for (int i = 0; i < 4; i++) {
            int task = i * 32 + lane;
            int rl   = task >> 3;            // 0..15
            int seg  = task & 7;             // 0..7
            float4 v = *(const float4*)(sTwp + rl * TROWF + seg * 4);
            int ro = sRout[it * TILE + wid * RPW + rl];
            red4(out + (size_t)ro * COUT + seg * 4, v.x, v.y, v.z, v.w);
        }
        __syncwarp();   // sT reuse gate for next iteration
    }
}

// ---------------------------------------------------------------------------
extern "C" void kernel_launch(void* const* d_in, const int* in_sizes, int n_in,
                              void* d_out, int out_size) {
    const float* feats  = (const float*)d_in[0];
    const float* weight = (const float*)d_in[1];
    const float* bias   = (const float*)d_in[2];
    const int*   rin    = (const int*)  d_in[3];
    const int*   rout   = (const int*)  d_in[4];
    float* out = (float*)d_out;

    const int total4 = NOUT * COUT / 4;
    init_out_kernel<<<(total4 + 255) / 256, 256>>>(out, bias);

    dim3 grid((RR + TPB - 1) / TPB, KK);
    mma_scatter_kernel<<<grid, NTHR>>>(feats, weight, rin, rout, out);
}

// round 17
// speedup vs baseline: 1.3823x; 1.0894x over previous
#include <cuda_runtime.h>
#include <cstdint>

// Problem constants
#define KK    8
#define RR    200000
#define CIN   32
#define COUT  32
#define NOUT  400000
#define TPB   512        // rules per block
#define NTHR  128        // 4 warps
#define WARPS 4
#define RPW   16         // rules per warp-tile
#define TILE  (WARPS * RPW)   // 64 rules per block iteration

// smem layout (bytes)
// A tile: AROW=64 (no pad) + chunk-XOR swizzle -> conflict-free STS and ldmatrix
#define AROW    64                  // bf16 row: 32 x 2B, 4 x 16B chunks
#define A_PLANE (16 * AROW)         // 1024 (one bf16 plane, 16 rows)
#define A_WARP  (2 * A_PLANE)       // 2048 (hi + lo planes)
#define OFF_A   0                   // 4 warps -> 8192
#define TROWF   40                  // transpose row pitch in floats (160B, conflict-free)
#define T_WARP  (16 * TROWF * 4)    // 2560
#define OFF_T   8192                // 4 warps -> 10240, end 18432
#define OFF_RIN  18432              // 512 ints
#define OFF_ROUT 20480              // 512 ints
#define SMEM_BYTES 22528

// ---------------------------------------------------------------------------
// helpers
// ---------------------------------------------------------------------------
__device__ __forceinline__ uint32_t smem_u32(const void* p) {
    uint32_t a;
    asm("{ .reg .u64 t; cvta.to.shared.u64 t, %1; cvt.u32.u64 %0, t; }" : "=r"(a) : "l"(p));
    return a;
}
__device__ __forceinline__ uint32_t cvt_bf16x2(float hi, float lo) {  // (hi<<16)|lo
    uint32_t r;
    asm("cvt.rn.bf16x2.f32 %0, %1, %2;" : "=r"(r) : "f"(hi), "f"(lo));
    return r;
}
__device__ __forceinline__ void sts64(uint32_t a, uint32_t x, uint32_t y) {
    asm volatile("st.shared.v2.b32 [%0], {%1,%2};" :: "r"(a), "r"(x), "r"(y));
}
__device__ __forceinline__ void red4(float* addr, float a, float b, float c, float d) {
    asm volatile("red.global.add.v4.f32 [%0], {%1,%2,%3,%4};"
                 :: "l"(addr), "f"(a), "f"(b), "f"(c), "f"(d) : "memory");
}
__device__ __forceinline__ void ldmx4(uint32_t* r, uint32_t addr) {
    asm volatile("ldmatrix.sync.aligned.m8n8.x4.shared.b16 {%0,%1,%2,%3}, [%4];"
                 : "=r"(r[0]), "=r"(r[1]), "=r"(r[2]), "=r"(r[3]) : "r"(addr));
}
__device__ __forceinline__ void mma_bf16(float* d, const uint32_t* a, const uint32_t* b) {
    asm volatile("mma.sync.aligned.m16n8k16.row.col.f32.bf16.bf16.f32 "
                 "{%0,%1,%2,%3}, {%4,%5,%6,%7}, {%8,%9}, {%0,%1,%2,%3};"
                 : "+f"(d[0]), "+f"(d[1]), "+f"(d[2]), "+f"(d[3])
                 : "r"(a[0]), "r"(a[1]), "r"(a[2]), "r"(a[3]), "r"(b[0]), "r"(b[1]));
}
// Streaming (evict-first) loads: use-once data must not evict the L2-resident output
__device__ __forceinline__ float4 ldcs4(const float4* p) {
    float4 v;
    asm volatile("ld.global.cs.v4.f32 {%0,%1,%2,%3}, [%4];"
                 : "=f"(v.x), "=f"(v.y), "=f"(v.z), "=f"(v.w) : "l"(p));
    return v;
}
__device__ __forceinline__ int4 ldcsi4(const int4* p) {
    int4 v;
    asm volatile("ld.global.cs.v4.b32 {%0,%1,%2,%3}, [%4];"
                 : "=r"(v.x), "=r"(v.y), "=r"(v.z), "=r"(v.w) : "l"(p));
    return v;
}

// ---------------------------------------------------------------------------
// Kernel 1: initialize output to bias
// ---------------------------------------------------------------------------
__global__ void init_out_kernel(float* __restrict__ out,
                                const float* __restrict__ bias) {
    int idx = blockIdx.x * blockDim.x + threadIdx.x;
    const int total4 = NOUT * COUT / 4;
    if (idx < total4) {
        int c = (idx & 7) * 4;
        float4 v = make_float4(bias[c], bias[c + 1], bias[c + 2], bias[c + 3]);
        reinterpret_cast<float4*>(out)[idx] = v;
    }
}

// ---------------------------------------------------------------------------
// Kernel 2: gather (streaming) -> bf16 hi/lo split -> mma.sync
//           -> smem transpose -> line-coalesced v4 RED
//   Conflict-free smem: A chunk-XOR swizzle (AROW=64), TROWF=40 transpose.
// ---------------------------------------------------------------------------
__global__ void __launch_bounds__(NTHR)
mma_scatter_kernel(const float* __restrict__ feats,
                   const float* __restrict__ weight,
                   const int*   __restrict__ rules_in,
                   const int*   __restrict__ rules_out,
                   float*       __restrict__ out)
{
    __shared__ __align__(128) char smem[SMEM_BYTES];
    const uint32_t sb = smem_u32(smem);
    const int tid  = threadIdx.x;
    const int lane = tid & 31;
    const int wid  = tid >> 5;
    const int g    = lane >> 2;       // mma group row
    const int t    = lane & 3;        // thread-in-group
    const int k    = blockIdx.y;
    const int base = blockIdx.x * TPB;
    const int nblk = min(TPB, RR - base);
    const int nit  = nblk / TILE;     // exact for these sizes

    int* sRin  = (int*)(smem + OFF_RIN);
    int* sRout = (int*)(smem + OFF_ROUT);

    // Stage rule indices (one int4 per thread covers TPB=512) — streaming
    {
        const int4* rin4  = (const int4*)(rules_in  + k * RR + base);
        const int4* rout4 = (const int4*)(rules_out + k * RR + base);
        if (tid * 4 < nblk) {
            ((int4*)sRin)[tid]  = ldcsi4(rin4  + tid);
            ((int4*)sRout)[tid] = ldcsi4(rout4 + tid);
        }
    }

    // Weight fragments (hi/lo split), B col-major for m16n8k16:
    //   reg0 = (B[k0+1][o]<<16)|B[k0][o], reg1 = (B[k0+9][o]<<16)|B[k0+8][o]
    //   k0 = kc*16 + 2t, o = n*8 + g
    uint32_t WH[4][2][2], WL[4][2][2];
    {
        const float* wk = weight + (size_t)k * CIN * COUT;
        #pragma unroll
        for (int n = 0; n < 4; n++)
            #pragma unroll
            for (int kc = 0; kc < 2; kc++) {
                int o  = n * 8 + g;
                int k0 = kc * 16 + 2 * t;
                float w00 = __ldg(wk + (k0 + 0) * COUT + o);
                float w01 = __ldg(wk + (k0 + 1) * COUT + o);
                float w10 = __ldg(wk + (k0 + 8) * COUT + o);
                float w11 = __ldg(wk + (k0 + 9) * COUT + o);
                uint32_t h0 = cvt_bf16x2(w01, w00);
                uint32_t h1 = cvt_bf16x2(w11, w10);
                WH[n][kc][0] = h0;
                WH[n][kc][1] = h1;
                float r00 = w00 - __uint_as_float(h0 << 16);
                float r01 = w01 - __uint_as_float(h0 & 0xFFFF0000u);
                float r10 = w10 - __uint_as_float(h1 << 16);
                float r11 = w11 - __uint_as_float(h1 & 0xFFFF0000u);
                WL[n][kc][0] = cvt_bf16x2(r01, r00);
                WL[n][kc][1] = cvt_bf16x2(r11, r10);
            }
    }
    __syncthreads();   // indices staged

    const uint32_t sAw = sb + OFF_A + wid * A_WARP;
    const uint32_t sTw = sb + OFF_T + wid * T_WARP;
    float* sTwp = (float*)(smem + OFF_T + wid * T_WARP);

    // ldmatrix lane addresses with chunk swizzle c' = c ^ ((row>>1)&3):
    //   lanes 0-7: rows 0-7 chunk base 0 | 8-15: rows 8-15 cb 0
    //   16-23: rows 0-7 cb 1 | 24-31: rows 8-15 cb 1; kc adds +2 to chunk.
    const int lm_row  = (lane & 7) + ((lane >> 3) & 1) * 8;
    const int lm_cb   = lane >> 4;                 // 0 or 1
    const int lm_swz  = (lm_row >> 1) & 3;
    const uint32_t lm_rowbase = sAw + lm_row * AROW;
    const uint32_t lmA0 = lm_rowbase + (uint32_t)(((lm_cb + 0) ^ lm_swz) << 4); // kc=0
    const uint32_t lmA1 = lm_rowbase + (uint32_t)(((lm_cb + 2) ^ lm_swz) << 4); // kc=1

    // Per-lane gather slots: row = i*4 + (lane>>3), seg = lane&7
    const int g_row = lane >> 3;
    const int g_seg = lane & 7;
    // Convert-STS swizzled chunk offset for this lane's (row-phase, seg):
    const int st_c    = g_seg >> 1;         // 16B chunk index 0..3
    const int st_half = (g_seg & 1) * 8;    // 8B half within chunk

    float4 gbuf[4];
    auto do_gather = [&](int it) {
        #pragma unroll
        for (int i = 0; i < 4; i++) {
            int r = sRin[it * TILE + wid * RPW + i * 4 + g_row];
            gbuf[i] = ldcs4((const float4*)(feats + (size_t)r * CIN) + g_seg);
        }
    };
    do_gather(0);

    for (int it = 0; it < nit; it++) {
        // ---- convert gathered f32 -> bf16 hi/lo planes in swizzled smem
        #pragma unroll
        for (int i = 0; i < 4; i++) {
            int row = i * 4 + g_row;
            int swz = (row >> 1) & 3;
            uint32_t a_hi = sAw + row * AROW + ((st_c ^ swz) << 4) + st_half;
            float4 v = gbuf[i];
            uint32_t h0 = cvt_bf16x2(v.y, v.x);
            uint32_t h1 = cvt_bf16x2(v.w, v.z);
            float hx = __uint_as_float(h0 << 16);
            float hy = __uint_as_float(h0 & 0xFFFF0000u);
            float hz = __uint_as_float(h1 << 16);
            float hw = __uint_as_float(h1 & 0xFFFF0000u);
            uint32_t l0 = cvt_bf16x2(v.y - hy, v.x - hx);
            uint32_t l1 = cvt_bf16x2(v.w - hw, v.z - hz);
            sts64(a_hi,           h0, h1);
            sts64(a_hi + A_PLANE, l0, l1);
        }
        if (it + 1 < nit) do_gather(it + 1);   // overlap LDG with mma/epilogue
        __syncwarp();

        // ---- load A fragments (hi and lo planes, 2 K-chunks each)
        uint32_t ah[2][4], al[2][4];
        ldmx4(ah[0], lmA0);
        ldmx4(ah[1], lmA1);
        ldmx4(al[0], lmA0 + A_PLANE);
        ldmx4(al[1], lmA1 + A_PLANE);

        // ---- 24 mma: D[n] = sum_kc Ah*Wh + Al*Wh + Ah*Wl
        float D[4][4] = {};
        #pragma unroll
        for (int n = 0; n < 4; n++)
            #pragma unroll
            for (int kc = 0; kc < 2; kc++) {
                mma_bf16(D[n], ah[kc], WH[n][kc]);
                mma_bf16(D[n], al[kc], WH[n][kc]);
                mma_bf16(D[n], ah[kc], WL[n][kc]);
            }

        // ---- epilogue: fragments -> smem transpose (TROWF=40, conflict-free)
        // D[n][0,1] = rule g,   cols n*8+2t, +1
        // D[n][2,3] = rule g+8, cols n*8+2t, +1
        #pragma unroll
        for (int n = 0; n < 4; n++) {
            int col = n * 8 + 2 * t;
            sts64(sTw + (g * TROWF + col) * 4,
                  __float_as_uint(D[n][0]), __float_as_uint(D[n][1]));
            sts64(sTw + ((g + 8) * TROWF + col) * 4,
                  __float_as_uint(D[n][2]), __float_as_uint(D[n][3]));
        }
        __syncwarp();

        // ---- coalesced wide scatter: 16 rules x 8 segs, one v4 RED each
        #pragma unroll
        for (int i = 0; i < 4; i++) {
            int task = i * 32 + lane;
            int rl   = task >> 3;            // 0..15
            int seg  = task & 7;             // 0..7
            float4 v = *(const float4*)(sTwp + rl * TROWF + seg * 4);
            int ro = sRout[it * TILE + wid * RPW + rl];
            red4(out + (size_t)ro * COUT + seg * 4, v.x, v.y, v.z, v.w);
        }
        __syncwarp();   // sT reuse gate for next iteration
    }
}

// ---------------------------------------------------------------------------
extern "C" void kernel_launch(void* const* d_in, const int* in_sizes, int n_in,
                              void* d_out, int out_size) {
    const float* feats  = (const float*)d_in[0];
    const float* weight = (const float*)d_in[1];
    const float* bias   = (const float*)d_in[2];
    const int*   rin    = (const int*)  d_in[3];
    const int*   rout   = (const int*)  d_in[4];
    float* out = (float*)d_out;

    const int total4 = NOUT * COUT / 4;
    init_out_kernel<<<(total4 + 255) / 256, 256>>>(out, bias);

    dim3 grid((RR + TPB - 1) / TPB, KK);
    mma_scatter_kernel<<<grid, NTHR>>>(feats, weight, rin, rout, out);
}